// round 14
// baseline (speedup 1.0000x reference)
#include <cuda_runtime.h>
#include <cuda_bf16.h>
#include <math.h>
#include <stdint.h>

// Problem constants
#define BATCH 8
#define LSEQ  1024
#define DMODEL 1024
#define NHEAD 16
#define DK 64

// ---------------------------------------------------------------------------
// Scratch (__device__ globals; allocation APIs forbidden)
//   g_f32 : QS[8M] KS[8M] VS[8M] CTX[8M] floats
//   g_wbf : WQh WQl WKh WKl WVh WVl WPh WPl (1M bf16 each), [N,K] row-major
// ---------------------------------------------------------------------------
#define M1 (1024u*1024u)
__device__ float          g_f32[(size_t)32 * M1];
__device__ __nv_bfloat16  g_wbf[(size_t)8  * M1];

// ======================= helpers ===========================================
__device__ __forceinline__ uint32_t smem_u32(const void* p) {
    uint32_t a;
    asm("{ .reg .u64 t; cvta.to.shared.u64 t, %1; cvt.u32.u64 %0, t; }"
        : "=r"(a) : "l"(p));
    return a;
}
__device__ __forceinline__ void ldsm4(uint32_t* r, uint32_t addr) {
    asm volatile("ldmatrix.sync.aligned.m8n8.x4.shared.b16 {%0,%1,%2,%3}, [%4];"
                 : "=r"(r[0]), "=r"(r[1]), "=r"(r[2]), "=r"(r[3]) : "r"(addr));
}
__device__ __forceinline__ void mma16816(float* d, const uint32_t* a, const uint32_t* b) {
    asm volatile(
        "mma.sync.aligned.m16n8k16.row.col.f32.bf16.bf16.f32 "
        "{%0,%1,%2,%3}, {%4,%5,%6,%7}, {%8,%9}, {%0,%1,%2,%3};"
        : "+f"(d[0]), "+f"(d[1]), "+f"(d[2]), "+f"(d[3])
        : "r"(a[0]), "r"(a[1]), "r"(a[2]), "r"(a[3]), "r"(b[0]), "r"(b[1]));
}
// split 4 floats into packed bf16 hi (2x u32? -> 2 u32 of 2 bf16) and lo
__device__ __forceinline__ void split4(float4 v, uint32_t& h0, uint32_t& h1,
                                       uint32_t& l0, uint32_t& l1) {
    __nv_bfloat162 ha = __floats2bfloat162_rn(v.x, v.y);
    __nv_bfloat162 hb = __floats2bfloat162_rn(v.z, v.w);
    float lx = v.x - __bfloat162float(ha.x);
    float ly = v.y - __bfloat162float(ha.y);
    float lz = v.z - __bfloat162float(hb.x);
    float lw = v.w - __bfloat162float(hb.y);
    __nv_bfloat162 la = __floats2bfloat162_rn(lx, ly);
    __nv_bfloat162 lb = __floats2bfloat162_rn(lz, lw);
    h0 = (uint32_t)__bfloat16_as_ushort(ha.x) | ((uint32_t)__bfloat16_as_ushort(ha.y) << 16);
    h1 = (uint32_t)__bfloat16_as_ushort(hb.x) | ((uint32_t)__bfloat16_as_ushort(hb.y) << 16);
    l0 = (uint32_t)__bfloat16_as_ushort(la.x) | ((uint32_t)__bfloat16_as_ushort(la.y) << 16);
    l1 = (uint32_t)__bfloat16_as_ushort(lb.x) | ((uint32_t)__bfloat16_as_ushort(lb.y) << 16);
}

// ======================= weight prep kernels ================================
// w_qs[h][d][kk] -> B^T[n=h*64+kk][k=d] bf16 hi/lo
__global__ void reshape_split_qkv(const float* __restrict__ w,
                                  __nv_bfloat16* __restrict__ hi,
                                  __nv_bfloat16* __restrict__ lo) {
    int i = blockIdx.x * 256 + threadIdx.x;   // 1M elements
    int n = i >> 10;
    int d = i & 1023;
    float v = w[((n >> 6) << 16) + (d << 6) + (n & 63)];
    __nv_bfloat16 h = __float2bfloat16(v);
    hi[i] = h;
    lo[i] = __float2bfloat16(v - __bfloat162float(h));
}
// proj_w is already [N,K] row-major; plain split
__global__ void split_bf16_kernel(const float4* __restrict__ x,
                                  uint2* __restrict__ hi, uint2* __restrict__ lo, int n4) {
    int i = blockIdx.x * 256 + threadIdx.x;
    if (i >= n4) return;
    uint32_t h0, h1, l0, l1;
    split4(x[i], h0, h1, l0, l1);
    hi[i] = make_uint2(h0, h1);
    lo[i] = make_uint2(l0, l1);
}

// ======================= mma.sync split-bf16 GEMM ===========================
// C[8192,1024] = A[8192,1024](fp32, converted inline) * B^T (bf16 hi/lo [N,K])
// acc = Ah*Bh + Ah*Bl + Al*Bh.  CTA 128x128, K-chunk 32, double-buffered smem.
// EPI==1: += bias[col] + resid[row,col]
#define GSTRIDE 80                 // padded smem row stride (bytes)
#define TILE_B  (128 * GSTRIDE)    // 10240
#define STAGE_B (4 * TILE_B)       // Ah Al Bh Bl
#define GEMM_SMEM (2 * STAGE_B)    // 81920

template <int EPI>
__global__ __launch_bounds__(256, 1)
void gemm_mma_kernel(const float* __restrict__ A,
                     const __nv_bfloat16* __restrict__ Bh,
                     const __nv_bfloat16* __restrict__ Bl,
                     float* __restrict__ C,
                     const float* __restrict__ bias,
                     const float* __restrict__ resid) {
    extern __shared__ __align__(128) char sm[];
    const int t = threadIdx.x;
    const int bx = blockIdx.x, by = blockIdx.y;
    const int wid = t >> 5, lane = t & 31;

    const float* Abase = A + (size_t)(by * 128) * 1024;
    const __nv_bfloat16* Bhb = Bh + (size_t)(bx * 128) * 1024;
    const __nv_bfloat16* Blb = Bl + (size_t)(bx * 128) * 1024;

    float4 ar[4];
    uint4  bhr[2], blr[2];

    const uint32_t smb = smem_u32(sm);
    const int wm = wid & 3;      // M warp (4 x 32 rows)
    const int wn = wid >> 2;     // N warp (2 x 64 cols)

    float acc[2][8][4];
#pragma unroll
    for (int mt = 0; mt < 2; mt++)
#pragma unroll
        for (int nt = 0; nt < 8; nt++)
#pragma unroll
            for (int j = 0; j < 4; j++) acc[mt][nt][j] = 0.0f;

    // ldmatrix base byte-offsets (within tile, k-offset added later)
    const uint32_t aoff = (uint32_t)((wm * 32 + (lane & 15)) * GSTRIDE + (lane >> 4) * 16);
    const uint32_t boff = (uint32_t)((wn * 64 + (lane & 7) + ((lane >> 4) & 1) * 8) * GSTRIDE
                                     + ((lane >> 3) & 1) * 16);

#define LOAD_REGS(k0)                                                         \
    {                                                                         \
        _Pragma("unroll")                                                     \
        for (int i = 0; i < 4; i++) {                                         \
            int idx = t + 256 * i, row = idx >> 3, seg = idx & 7;             \
            ar[i] = *(const float4*)(Abase + (size_t)row * 1024 + (k0) + seg * 4); \
        }                                                                     \
        _Pragma("unroll")                                                     \
        for (int i = 0; i < 2; i++) {                                         \
            int idx = t + 256 * i, row = idx >> 2, seg = idx & 3;             \
            const char* ph = (const char*)(Bhb + (size_t)row * 1024 + (k0)) + seg * 16; \
            const char* pl = (const char*)(Blb + (size_t)row * 1024 + (k0)) + seg * 16; \
            bhr[i] = *(const uint4*)ph;                                       \
            blr[i] = *(const uint4*)pl;                                       \
        }                                                                     \
    }

#define STORE_SMEM(buf)                                                      \
    {                                                                         \
        char* AH = sm + (buf) * STAGE_B;                                      \
        char* AL = AH + TILE_B;                                               \
        char* BHs = AH + 2 * TILE_B;                                          \
        char* BLs = AH + 3 * TILE_B;                                          \
        _Pragma("unroll")                                                     \
        for (int i = 0; i < 4; i++) {                                         \
            int idx = t + 256 * i, row = idx >> 3, seg = idx & 7;             \
            uint32_t h0, h1, l0, l1;                                          \
            split4(ar[i], h0, h1, l0, l1);                                    \
            *(uint2*)(AH + row * GSTRIDE + seg * 8) = make_uint2(h0, h1);     \
            *(uint2*)(AL + row * GSTRIDE + seg * 8) = make_uint2(l0, l1);     \
        }                                                                     \
        _Pragma("unroll")                                                     \
        for (int i = 0; i < 2; i++) {                                         \
            int idx = t + 256 * i, row = idx >> 2, seg = idx & 3;             \
            *(uint4*)(BHs + row * GSTRIDE + seg * 16) = bhr[i];               \
            *(uint4*)(BLs + row * GSTRIDE + seg * 16) = blr[i];               \
        }                                                                     \
    }

    LOAD_REGS(0);
    STORE_SMEM(0);
    __syncthreads();

    for (int c = 0; c < 32; c++) {
        const int buf = c & 1;
        if (c + 1 < 32) LOAD_REGS((c + 1) * 32);

        const uint32_t AHb = smb + buf * STAGE_B;
        const uint32_t ALb = AHb + TILE_B;
        const uint32_t BHt = AHb + 2 * TILE_B;
        const uint32_t BLt = AHb + 3 * TILE_B;
#pragma unroll
        for (int ks = 0; ks < 2; ks++) {
            const uint32_t kb = ks * 32;
            uint32_t ah[2][4], al[2][4], bh[8][2], bl[8][2];
#pragma unroll
            for (int mt = 0; mt < 2; mt++) {
                ldsm4(ah[mt], AHb + aoff + mt * 16 * GSTRIDE + kb);
                ldsm4(al[mt], ALb + aoff + mt * 16 * GSTRIDE + kb);
            }
#pragma unroll
            for (int p = 0; p < 4; p++) {
                uint32_t r[4];
                ldsm4(r, BHt + boff + p * 16 * GSTRIDE + kb);
                bh[2 * p][0] = r[0]; bh[2 * p][1] = r[1];
                bh[2 * p + 1][0] = r[2]; bh[2 * p + 1][1] = r[3];
                ldsm4(r, BLt + boff + p * 16 * GSTRIDE + kb);
                bl[2 * p][0] = r[0]; bl[2 * p][1] = r[1];
                bl[2 * p + 1][0] = r[2]; bl[2 * p + 1][1] = r[3];
            }
#pragma unroll
            for (int mt = 0; mt < 2; mt++)
#pragma unroll
                for (int nt = 0; nt < 8; nt++) {
                    mma16816(acc[mt][nt], ah[mt], bh[nt]);
                    mma16816(acc[mt][nt], ah[mt], bl[nt]);
                    mma16816(acc[mt][nt], al[mt], bh[nt]);
                }
        }
        if (c + 1 < 32) {
            STORE_SMEM(buf ^ 1);
            __syncthreads();
        }
    }

    // epilogue: d frag mapping r0 = lane>>2 (+8), c0 = (lane&3)*2 (+1)
    const int r0 = lane >> 2, c0 = (lane & 3) * 2;
#pragma unroll
    for (int mt = 0; mt < 2; mt++)
#pragma unroll
        for (int nt = 0; nt < 8; nt++)
#pragma unroll
            for (int half = 0; half < 2; half++) {
                int row = by * 128 + wm * 32 + mt * 16 + r0 + half * 8;
                int col = bx * 128 + wn * 64 + nt * 8 + c0;
                float2 v = make_float2(acc[mt][nt][half * 2], acc[mt][nt][half * 2 + 1]);
                size_t idx = (size_t)row * 1024 + col;
                if (EPI) {
                    v.x += bias[col]     + resid[idx];
                    v.y += bias[col + 1] + resid[idx + 1];
                }
                *(float2*)(C + idx) = v;
            }
}

// ---------------------------------------------------------------------------
// Fused attention (unchanged from passing R9 kernel)
// ---------------------------------------------------------------------------
#define TQ 32
#define TKC 128
#define LP (LSEQ + 1)
#define ATTN_SMEM ((TQ * LP + TQ * DK + TKC * 65) * 4)

__global__ __launch_bounds__(256, 1)
void attn_kernel(const float* __restrict__ qs, const float* __restrict__ ks,
                 const float* __restrict__ vs, const unsigned char* __restrict__ mask,
                 float* __restrict__ attn_out, float* __restrict__ ctx) {
    extern __shared__ float smf[];
    float* Ss = smf;                   // TQ x LP
    float* Qs = Ss + TQ * LP;          // TQ x DK
    float* KV = Qs + TQ * DK;          // TKC x 65

    const int h = blockIdx.z, b = blockIdx.y;
    const int q0 = blockIdx.x * TQ;
    const int t = threadIdx.x;
    const int hd = h * DK;
    const float inv_temper = 1.0f / 32.0f;   // 1/sqrt(D_MODEL)
    const float NEG_INF = __int_as_float(0xff800000);

    {
        int r = t >> 4;
        int c4 = (t & 15) << 2;
#pragma unroll
        for (int rep = 0; rep < 2; rep++) {
            int rr = r + rep * 16;
            float4 v = *(const float4*)(qs + ((size_t)(b * LSEQ + q0 + rr)) * 1024 + hd + c4);
            *(float4*)&Qs[rr * DK + c4] = v;
        }
    }

    const int tr = t >> 5;
    const int tc = t & 31;

    for (int kk0 = 0; kk0 < LSEQ; kk0 += TKC) {
        __syncthreads();
        {
            int lk = t >> 4;
            int c4 = (t & 15) << 2;
#pragma unroll
            for (int rep = 0; rep < 8; rep++) {
                int kkl = lk + rep * 16;
                float4 v = *(const float4*)(ks + ((size_t)(b * LSEQ + kk0 + kkl)) * 1024 + hd + c4);
                KV[kkl * 65 + c4 + 0] = v.x;
                KV[kkl * 65 + c4 + 1] = v.y;
                KV[kkl * 65 + c4 + 2] = v.z;
                KV[kkl * 65 + c4 + 3] = v.w;
            }
        }
        __syncthreads();
        float acc[4][4] = {};
#pragma unroll
        for (int d = 0; d < DK; d++) {
            float qv[4], kv[4];
#pragma unroll
            for (int i = 0; i < 4; i++) qv[i] = Qs[(tr * 4 + i) * DK + d];
#pragma unroll
            for (int j = 0; j < 4; j++) kv[j] = KV[(tc + 32 * j) * 65 + d];
#pragma unroll
            for (int i = 0; i < 4; i++)
#pragma unroll
                for (int j = 0; j < 4; j++) acc[i][j] += qv[i] * kv[j];
        }
#pragma unroll
        for (int i = 0; i < 4; i++)
#pragma unroll
            for (int j = 0; j < 4; j++)
                Ss[(tr * 4 + i) * LP + kk0 + tc + 32 * j] = acc[i][j] * inv_temper;
    }
    __syncthreads();

    {
        const int lane = tc;
        const unsigned char* mbase = mask + ((size_t)b * LSEQ + q0) * LSEQ;
#pragma unroll
        for (int i = 0; i < 4; i++) {
            int r = tr * 4 + i;
            float* srow = Ss + r * LP;
            const unsigned char* mr = mbase + (size_t)r * LSEQ;
            float m = NEG_INF;
            for (int c = lane; c < LSEQ; c += 32) {
                float v = srow[c];
                if (mr[c]) { v = NEG_INF; srow[c] = v; }
                m = fmaxf(m, v);
            }
#pragma unroll
            for (int o = 16; o > 0; o >>= 1) m = fmaxf(m, __shfl_xor_sync(0xffffffffu, m, o));
            float s = 0.0f;
            for (int c = lane; c < LSEQ; c += 32) {
                float p = __expf(srow[c] - m);
                srow[c] = p;
                s += p;
            }
#pragma unroll
            for (int o = 16; o > 0; o >>= 1) s += __shfl_xor_sync(0xffffffffu, s, o);
            float inv = 1.0f / s;
            float* arow = attn_out + (((size_t)(h * BATCH + b)) * LSEQ + q0 + r) * LSEQ;
            for (int c = lane; c < LSEQ; c += 32) {
                float p = srow[c] * inv;
                srow[c] = p;
                arow[c] = p;
            }
        }
    }
    __syncthreads();

    float oacc[4][2] = {};
    for (int kk0 = 0; kk0 < LSEQ; kk0 += TKC) {
        __syncthreads();
        {
            int lk = t >> 4;
            int c4 = (t & 15) << 2;
#pragma unroll
            for (int rep = 0; rep < 8; rep++) {
                int kkl = lk + rep * 16;
                float4 v = *(const float4*)(vs + ((size_t)(b * LSEQ + kk0 + kkl)) * 1024 + hd + c4);
                KV[kkl * 65 + c4 + 0] = v.x;
                KV[kkl * 65 + c4 + 1] = v.y;
                KV[kkl * 65 + c4 + 2] = v.z;
                KV[kkl * 65 + c4 + 3] = v.w;
            }
        }
        __syncthreads();
#pragma unroll 4
        for (int kk = 0; kk < TKC; kk++) {
            float pv[4], vv[2];
#pragma unroll
            for (int i = 0; i < 4; i++) pv[i] = Ss[(tr * 4 + i) * LP + kk0 + kk];
            vv[0] = KV[kk * 65 + tc];
            vv[1] = KV[kk * 65 + tc + 32];
#pragma unroll
            for (int i = 0; i < 4; i++) {
                oacc[i][0] += pv[i] * vv[0];
                oacc[i][1] += pv[i] * vv[1];
            }
        }
    }
#pragma unroll
    for (int i = 0; i < 4; i++) {
        size_t base = ((size_t)(b * LSEQ + q0 + tr * 4 + i)) * 1024 + hd;
        ctx[base + tc]      = oacc[i][0];
        ctx[base + tc + 32] = oacc[i][1];
    }
}

// ---------------------------------------------------------------------------
// In-place LayerNorm
// ---------------------------------------------------------------------------
__global__ void ln_kernel(float* __restrict__ y,
                          const float* __restrict__ gamma,
                          const float* __restrict__ beta) {
    __shared__ float red[18];
    const int row = blockIdx.x;
    const int t = threadIdx.x;
    float* p = y + (size_t)row * 1024;
    float v[4];
    float s = 0.0f, s2 = 0.0f;
#pragma unroll
    for (int j = 0; j < 4; j++) {
        v[j] = p[t + 256 * j];
        s += v[j];
        s2 += v[j] * v[j];
    }
#pragma unroll
    for (int o = 16; o > 0; o >>= 1) {
        s  += __shfl_xor_sync(0xffffffffu, s, o);
        s2 += __shfl_xor_sync(0xffffffffu, s2, o);
    }
    int warp = t >> 5, lane = t & 31;
    if (lane == 0) { red[warp] = s; red[8 + warp] = s2; }
    __syncthreads();
    if (t == 0) {
        float a = 0.0f, bsum = 0.0f;
#pragma unroll
        for (int w = 0; w < 8; w++) { a += red[w]; bsum += red[8 + w]; }
        red[16] = a; red[17] = bsum;
    }
    __syncthreads();
    float mean = red[16] * (1.0f / 1024.0f);
    float var  = red[17] * (1.0f / 1024.0f) - mean * mean;
    float inv  = rsqrtf(var + 1e-5f);
#pragma unroll
    for (int j = 0; j < 4; j++) {
        int c = t + 256 * j;
        p[c] = (v[j] - mean) * inv * gamma[c] + beta[c];
    }
}

// ---------------------------------------------------------------------------
// kernel_launch
// Inputs: q, k, v, attn_mask(bool), w_qs, w_ks, w_vs, proj_w, proj_b,
//         ln_gamma, ln_beta
// d_out: [outputs 8192*1024 f32][attns 128*1024*1024 f32]
// ---------------------------------------------------------------------------
extern "C" void kernel_launch(void* const* d_in, const int* in_sizes, int n_in,
                              void* d_out, int out_size) {
    const float* q      = (const float*)d_in[0];
    const float* k      = (const float*)d_in[1];
    const float* v      = (const float*)d_in[2];
    const unsigned char* mask = (const unsigned char*)d_in[3];
    const float* w_qs   = (const float*)d_in[4];
    const float* w_ks   = (const float*)d_in[5];
    const float* w_vs   = (const float*)d_in[6];
    const float* proj_w = (const float*)d_in[7];
    const float* proj_b = (const float*)d_in[8];
    const float* gamma  = (const float*)d_in[9];
    const float* beta   = (const float*)d_in[10];

    float* out = (float*)d_out;
    float* attn_out = out + (size_t)8192 * 1024;

    float* F = nullptr;  __nv_bfloat16* WB = nullptr;
    cudaGetSymbolAddress((void**)&F,  g_f32);
    cudaGetSymbolAddress((void**)&WB, g_wbf);

    float* QS  = F;
    float* KS  = F + (size_t)8  * M1;
    float* VS  = F + (size_t)16 * M1;
    float* CTX = F + (size_t)24 * M1;

    __nv_bfloat16* WQh = WB + 0 * M1; __nv_bfloat16* WQl = WB + 1 * M1;
    __nv_bfloat16* WKh = WB + 2 * M1; __nv_bfloat16* WKl = WB + 3 * M1;
    __nv_bfloat16* WVh = WB + 4 * M1; __nv_bfloat16* WVl = WB + 5 * M1;
    __nv_bfloat16* WPh = WB + 6 * M1; __nv_bfloat16* WPl = WB + 7 * M1;

    cudaFuncSetAttribute(gemm_mma_kernel<0>, cudaFuncAttributeMaxDynamicSharedMemorySize, GEMM_SMEM);
    cudaFuncSetAttribute(gemm_mma_kernel<1>, cudaFuncAttributeMaxDynamicSharedMemorySize, GEMM_SMEM);
    cudaFuncSetAttribute(attn_kernel, cudaFuncAttributeMaxDynamicSharedMemorySize, ATTN_SMEM);

    // weights -> bf16 hi/lo in [N,K] layout
    reshape_split_qkv<<<4096, 256>>>(w_qs, WQh, WQl);
    reshape_split_qkv<<<4096, 256>>>(w_ks, WKh, WKl);
    reshape_split_qkv<<<4096, 256>>>(w_vs, WVh, WVl);
    split_bf16_kernel<<<1024, 256>>>((const float4*)proj_w, (uint2*)WPh, (uint2*)WPl, 256 * 1024);

    const dim3 gg(8, 64);   // N blocks x M blocks

    // QKV projections (A = fp32 input, converted inline)
    gemm_mma_kernel<0><<<gg, 256, GEMM_SMEM>>>(q, WQh, WQl, QS, nullptr, nullptr);
    gemm_mma_kernel<0><<<gg, 256, GEMM_SMEM>>>(k, WKh, WKl, KS, nullptr, nullptr);
    gemm_mma_kernel<0><<<gg, 256, GEMM_SMEM>>>(v, WVh, WVl, VS, nullptr, nullptr);

    // fused attention (writes attn_out + CTX)
    attn_kernel<<<dim3(LSEQ / TQ, BATCH, NHEAD), 256, ATTN_SMEM>>>(QS, KS, VS, mask, attn_out, CTX);

    // output projection + bias + residual, then in-place LayerNorm
    gemm_mma_kernel<1><<<gg, 256, GEMM_SMEM>>>(CTX, WPh, WPl, out, proj_b, q);
    ln_kernel<<<8192, 256>>>(out, gamma, beta);
}

// round 15
// speedup vs baseline: 1.9169x; 1.9169x over previous
#include <cuda_runtime.h>
#include <cuda_bf16.h>
#include <math.h>
#include <stdint.h>

// Problem constants
#define BATCH 8
#define LSEQ  1024
#define DMODEL 1024
#define NHEAD 16
#define DK 64

// ---------------------------------------------------------------------------
// Scratch (__device__ globals)
//   g_f32 : QS[8M] KS[8M] VS[8M] CTX[8M] floats
//   g_wbf : WQh WQl WKh WKl WVh WVl WPh WPl (1M bf16 each)  [N,K] row-major
//           + VTh[8M] VTl[8M]  (V transposed per (h,b): [hb][n=64][k=1024])
// ---------------------------------------------------------------------------
#define M1 (1024u*1024u)
__device__ float          g_f32[(size_t)32 * M1];
__device__ __nv_bfloat16  g_wbf[(size_t)24 * M1];

// ======================= helpers ===========================================
__device__ __forceinline__ uint32_t smem_u32(const void* p) {
    uint32_t a;
    asm("{ .reg .u64 t; cvta.to.shared.u64 t, %1; cvt.u32.u64 %0, t; }"
        : "=r"(a) : "l"(p));
    return a;
}
__device__ __forceinline__ void ldsm4(uint32_t* r, uint32_t addr) {
    asm volatile("ldmatrix.sync.aligned.m8n8.x4.shared.b16 {%0,%1,%2,%3}, [%4];"
                 : "=r"(r[0]), "=r"(r[1]), "=r"(r[2]), "=r"(r[3]) : "r"(addr));
}
__device__ __forceinline__ void mma16816(float* d, const uint32_t* a, const uint32_t* b) {
    asm volatile(
        "mma.sync.aligned.m16n8k16.row.col.f32.bf16.bf16.f32 "
        "{%0,%1,%2,%3}, {%4,%5,%6,%7}, {%8,%9}, {%0,%1,%2,%3};"
        : "+f"(d[0]), "+f"(d[1]), "+f"(d[2]), "+f"(d[3])
        : "r"(a[0]), "r"(a[1]), "r"(a[2]), "r"(a[3]), "r"(b[0]), "r"(b[1]));
}
__device__ __forceinline__ void split4(float4 v, uint32_t& h0, uint32_t& h1,
                                       uint32_t& l0, uint32_t& l1) {
    __nv_bfloat162 ha = __floats2bfloat162_rn(v.x, v.y);
    __nv_bfloat162 hb = __floats2bfloat162_rn(v.z, v.w);
    float lx = v.x - __bfloat162float(ha.x);
    float ly = v.y - __bfloat162float(ha.y);
    float lz = v.z - __bfloat162float(hb.x);
    float lw = v.w - __bfloat162float(hb.y);
    __nv_bfloat162 la = __floats2bfloat162_rn(lx, ly);
    __nv_bfloat162 lb = __floats2bfloat162_rn(lz, lw);
    h0 = (uint32_t)__bfloat16_as_ushort(ha.x) | ((uint32_t)__bfloat16_as_ushort(ha.y) << 16);
    h1 = (uint32_t)__bfloat16_as_ushort(hb.x) | ((uint32_t)__bfloat16_as_ushort(hb.y) << 16);
    l0 = (uint32_t)__bfloat16_as_ushort(la.x) | ((uint32_t)__bfloat16_as_ushort(la.y) << 16);
    l1 = (uint32_t)__bfloat16_as_ushort(lb.x) | ((uint32_t)__bfloat16_as_ushort(lb.y) << 16);
}

// ======================= weight prep kernels ================================
__global__ void reshape_split_qkv(const float* __restrict__ w,
                                  __nv_bfloat16* __restrict__ hi,
                                  __nv_bfloat16* __restrict__ lo) {
    int i = blockIdx.x * 256 + threadIdx.x;   // 1M
    int n = i >> 10;
    int d = i & 1023;
    float v = w[((n >> 6) << 16) + (d << 6) + (n & 63)];
    __nv_bfloat16 h = __float2bfloat16(v);
    hi[i] = h;
    lo[i] = __float2bfloat16(v - __bfloat162float(h));
}
__global__ void split_bf16_kernel(const float4* __restrict__ x,
                                  uint2* __restrict__ hi, uint2* __restrict__ lo, int n4) {
    int i = blockIdx.x * 256 + threadIdx.x;
    if (i >= n4) return;
    uint32_t h0, h1, l0, l1;
    split4(x[i], h0, h1, l0, l1);
    hi[i] = make_uint2(h0, h1);
    lo[i] = make_uint2(l0, l1);
}

// VS fp32 [b*1024+k][h*64+n]  ->  VT bf16 hi/lo [(h*8+b)*64+n][k]
__global__ void vtrans_kernel(const float* __restrict__ vs,
                              __nv_bfloat16* __restrict__ vth,
                              __nv_bfloat16* __restrict__ vtl) {
    __shared__ float tile[32][33];
    const int k0 = blockIdx.x * 32;
    const int n0 = blockIdx.y * 32;
    const int z  = blockIdx.z;         // h*8+b
    const int h = z >> 3, b = z & 7;
    const int tx = threadIdx.x, ty = threadIdx.y;   // (32,8)
    for (int r = ty; r < 32; r += 8)
        tile[r][tx] = vs[(size_t)(b * 1024 + k0 + r) * 1024 + h * 64 + n0 + tx];
    __syncthreads();
    for (int r = ty; r < 32; r += 8) {
        float v = tile[tx][r];
        __nv_bfloat16 hv = __float2bfloat16(v);
        size_t o = (size_t)(z * 64 + n0 + r) * 1024 + k0 + tx;
        vth[o] = hv;
        vtl[o] = __float2bfloat16(v - __bfloat162float(hv));
    }
}

// ======================= mma.sync split-bf16 GEMM (projections) =============
#define GSTRIDE 80
#define TILE_B  (128 * GSTRIDE)
#define STAGE_B (4 * TILE_B)
#define GEMM_SMEM (2 * STAGE_B)

template <int EPI>
__global__ __launch_bounds__(256, 1)
void gemm_mma_kernel(const float* __restrict__ A,
                     const __nv_bfloat16* __restrict__ Bh,
                     const __nv_bfloat16* __restrict__ Bl,
                     float* __restrict__ C,
                     const float* __restrict__ bias,
                     const float* __restrict__ resid) {
    extern __shared__ __align__(128) char sm[];
    const int t = threadIdx.x;
    const int bx = blockIdx.x, by = blockIdx.y;
    const int wid = t >> 5, lane = t & 31;

    const float* Abase = A + (size_t)(by * 128) * 1024;
    const __nv_bfloat16* Bhb = Bh + (size_t)(bx * 128) * 1024;
    const __nv_bfloat16* Blb = Bl + (size_t)(bx * 128) * 1024;

    float4 ar[4];
    uint4  bhr[2], blr[2];

    const uint32_t smb = smem_u32(sm);
    const int wm = wid & 3;
    const int wn = wid >> 2;

    float acc[2][8][4];
#pragma unroll
    for (int mt = 0; mt < 2; mt++)
#pragma unroll
        for (int nt = 0; nt < 8; nt++)
#pragma unroll
            for (int j = 0; j < 4; j++) acc[mt][nt][j] = 0.0f;

    const uint32_t aoff = (uint32_t)((wm * 32 + (lane & 15)) * GSTRIDE + (lane >> 4) * 16);
    const uint32_t boff = (uint32_t)((wn * 64 + (lane & 7) + ((lane >> 4) & 1) * 8) * GSTRIDE
                                     + ((lane >> 3) & 1) * 16);

#define LOAD_REGS(k0)                                                         \
    {                                                                         \
        _Pragma("unroll")                                                     \
        for (int i = 0; i < 4; i++) {                                         \
            int idx = t + 256 * i, row = idx >> 3, seg = idx & 7;             \
            ar[i] = *(const float4*)(Abase + (size_t)row * 1024 + (k0) + seg * 4); \
        }                                                                     \
        _Pragma("unroll")                                                     \
        for (int i = 0; i < 2; i++) {                                         \
            int idx = t + 256 * i, row = idx >> 2, seg = idx & 3;             \
            const char* ph = (const char*)(Bhb + (size_t)row * 1024 + (k0)) + seg * 16; \
            const char* pl = (const char*)(Blb + (size_t)row * 1024 + (k0)) + seg * 16; \
            bhr[i] = *(const uint4*)ph;                                       \
            blr[i] = *(const uint4*)pl;                                       \
        }                                                                     \
    }

#define STORE_SMEM(buf)                                                      \
    {                                                                         \
        char* AH = sm + (buf) * STAGE_B;                                      \
        char* AL = AH + TILE_B;                                               \
        char* BHs = AH + 2 * TILE_B;                                          \
        char* BLs = AH + 3 * TILE_B;                                          \
        _Pragma("unroll")                                                     \
        for (int i = 0; i < 4; i++) {                                         \
            int idx = t + 256 * i, row = idx >> 3, seg = idx & 7;             \
            uint32_t h0, h1, l0, l1;                                          \
            split4(ar[i], h0, h1, l0, l1);                                    \
            *(uint2*)(AH + row * GSTRIDE + seg * 8) = make_uint2(h0, h1);     \
            *(uint2*)(AL + row * GSTRIDE + seg * 8) = make_uint2(l0, l1);     \
        }                                                                     \
        _Pragma("unroll")                                                     \
        for (int i = 0; i < 2; i++) {                                         \
            int idx = t + 256 * i, row = idx >> 2, seg = idx & 3;             \
            *(uint4*)(BHs + row * GSTRIDE + seg * 16) = bhr[i];               \
            *(uint4*)(BLs + row * GSTRIDE + seg * 16) = blr[i];               \
        }                                                                     \
    }

    LOAD_REGS(0);
    STORE_SMEM(0);
    __syncthreads();

    for (int c = 0; c < 32; c++) {
        const int buf = c & 1;
        if (c + 1 < 32) LOAD_REGS((c + 1) * 32);

        const uint32_t AHb = smb + buf * STAGE_B;
        const uint32_t ALb = AHb + TILE_B;
        const uint32_t BHt = AHb + 2 * TILE_B;
        const uint32_t BLt = AHb + 3 * TILE_B;
#pragma unroll
        for (int ks = 0; ks < 2; ks++) {
            const uint32_t kb = ks * 32;
            uint32_t ah[2][4], al[2][4], bh[8][2], bl[8][2];
#pragma unroll
            for (int mt = 0; mt < 2; mt++) {
                ldsm4(ah[mt], AHb + aoff + mt * 16 * GSTRIDE + kb);
                ldsm4(al[mt], ALb + aoff + mt * 16 * GSTRIDE + kb);
            }
#pragma unroll
            for (int p = 0; p < 4; p++) {
                uint32_t r[4];
                ldsm4(r, BHt + boff + p * 16 * GSTRIDE + kb);
                bh[2 * p][0] = r[0]; bh[2 * p][1] = r[1];
                bh[2 * p + 1][0] = r[2]; bh[2 * p + 1][1] = r[3];
                ldsm4(r, BLt + boff + p * 16 * GSTRIDE + kb);
                bl[2 * p][0] = r[0]; bl[2 * p][1] = r[1];
                bl[2 * p + 1][0] = r[2]; bl[2 * p + 1][1] = r[3];
            }
#pragma unroll
            for (int mt = 0; mt < 2; mt++)
#pragma unroll
                for (int nt = 0; nt < 8; nt++) {
                    mma16816(acc[mt][nt], ah[mt], bh[nt]);
                    mma16816(acc[mt][nt], ah[mt], bl[nt]);
                    mma16816(acc[mt][nt], al[mt], bh[nt]);
                }
        }
        if (c + 1 < 32) {
            STORE_SMEM(buf ^ 1);
            __syncthreads();
        }
    }

    const int r0 = lane >> 2, c0 = (lane & 3) * 2;
#pragma unroll
    for (int mt = 0; mt < 2; mt++)
#pragma unroll
        for (int nt = 0; nt < 8; nt++)
#pragma unroll
            for (int half = 0; half < 2; half++) {
                int row = by * 128 + wm * 32 + mt * 16 + r0 + half * 8;
                int col = bx * 128 + wn * 64 + nt * 8 + c0;
                float2 v = make_float2(acc[mt][nt][half * 2], acc[mt][nt][half * 2 + 1]);
                size_t idx = (size_t)row * 1024 + col;
                if (EPI) {
                    v.x += bias[col]     + resid[idx];
                    v.y += bias[col + 1] + resid[idx + 1];
                }
                *(float2*)(C + idx) = v;
            }
#undef LOAD_REGS
#undef STORE_SMEM
}

// ======================= attention pass 1: S = QK^T / 32 ====================
// Per (h,b): M=N=1024, K=64. Both operands fp32, split inline. 128x128 tiles.
#define QKSTRIDE 144
#define QK_TILE (128 * QKSTRIDE)     // 18432
#define QK_SMEM (4 * QK_TILE)        // 73728

__global__ __launch_bounds__(256, 1)
void qk_kernel(const float* __restrict__ qs, const float* __restrict__ ks,
               float* __restrict__ attn) {
    extern __shared__ __align__(128) char sm[];
    const int t = threadIdx.x;
    const int wid = t >> 5, lane = t & 31;
    const int bx = blockIdx.x, by = blockIdx.y, z = blockIdx.z;  // z = h*8+b
    const int h = z >> 3, b = z & 7;

    const float* Ab = qs + (size_t)(b * 1024 + by * 128) * 1024 + h * 64;
    const float* Bb = ks + (size_t)(b * 1024 + bx * 128) * 1024 + h * 64;

    char* AH = sm;
    char* AL = AH + QK_TILE;
    char* BH = AH + 2 * QK_TILE;
    char* BL = AH + 3 * QK_TILE;

    // load + split both 128x64 fp32 tiles (8 float4 per thread per operand)
#pragma unroll
    for (int i = 0; i < 8; i++) {
        int idx = t + 256 * i, row = idx >> 4, seg = idx & 15;
        float4 va = *(const float4*)(Ab + (size_t)row * 1024 + seg * 4);
        uint32_t h0, h1, l0, l1;
        split4(va, h0, h1, l0, l1);
        *(uint2*)(AH + row * QKSTRIDE + seg * 8) = make_uint2(h0, h1);
        *(uint2*)(AL + row * QKSTRIDE + seg * 8) = make_uint2(l0, l1);
        float4 vb = *(const float4*)(Bb + (size_t)row * 1024 + seg * 4);
        split4(vb, h0, h1, l0, l1);
        *(uint2*)(BH + row * QKSTRIDE + seg * 8) = make_uint2(h0, h1);
        *(uint2*)(BL + row * QKSTRIDE + seg * 8) = make_uint2(l0, l1);
    }
    __syncthreads();

    const uint32_t smb = smem_u32(sm);
    const int wm = wid & 3;   // 4 x 32 rows
    const int wn = wid >> 2;  // 2 x 64 cols
    const uint32_t aoff = (uint32_t)((wm * 32 + (lane & 15)) * QKSTRIDE + (lane >> 4) * 16);
    const uint32_t boff = (uint32_t)((wn * 64 + (lane & 7) + ((lane >> 4) & 1) * 8) * QKSTRIDE
                                     + ((lane >> 3) & 1) * 16);
    const uint32_t AHb = smb, ALb = smb + QK_TILE, BHt = smb + 2 * QK_TILE, BLt = smb + 3 * QK_TILE;

    float acc[2][8][4];
#pragma unroll
    for (int mt = 0; mt < 2; mt++)
#pragma unroll
        for (int nt = 0; nt < 8; nt++)
#pragma unroll
            for (int j = 0; j < 4; j++) acc[mt][nt][j] = 0.0f;

#pragma unroll
    for (int ksd = 0; ksd < 4; ksd++) {
        const uint32_t kb = ksd * 32;
        uint32_t ah[2][4], al[2][4], bh[8][2], bl[8][2];
#pragma unroll
        for (int mt = 0; mt < 2; mt++) {
            ldsm4(ah[mt], AHb + aoff + mt * 16 * QKSTRIDE + kb);
            ldsm4(al[mt], ALb + aoff + mt * 16 * QKSTRIDE + kb);
        }
#pragma unroll
        for (int p = 0; p < 4; p++) {
            uint32_t r[4];
            ldsm4(r, BHt + boff + p * 16 * QKSTRIDE + kb);
            bh[2 * p][0] = r[0]; bh[2 * p][1] = r[1];
            bh[2 * p + 1][0] = r[2]; bh[2 * p + 1][1] = r[3];
            ldsm4(r, BLt + boff + p * 16 * QKSTRIDE + kb);
            bl[2 * p][0] = r[0]; bl[2 * p][1] = r[1];
            bl[2 * p + 1][0] = r[2]; bl[2 * p + 1][1] = r[3];
        }
#pragma unroll
        for (int mt = 0; mt < 2; mt++)
#pragma unroll
            for (int nt = 0; nt < 8; nt++) {
                mma16816(acc[mt][nt], ah[mt], bh[nt]);
                mma16816(acc[mt][nt], ah[mt], bl[nt]);
                mma16816(acc[mt][nt], al[mt], bh[nt]);
            }
    }

    float* out = attn + (size_t)z * 1024 * 1024;
    const float scale = 1.0f / 32.0f;
    const int r0 = lane >> 2, c0 = (lane & 3) * 2;
#pragma unroll
    for (int mt = 0; mt < 2; mt++)
#pragma unroll
        for (int nt = 0; nt < 8; nt++)
#pragma unroll
            for (int half = 0; half < 2; half++) {
                int row = by * 128 + wm * 32 + mt * 16 + r0 + half * 8;
                int col = bx * 128 + wn * 64 + nt * 8 + c0;
                float2 v = make_float2(acc[mt][nt][half * 2] * scale,
                                       acc[mt][nt][half * 2 + 1] * scale);
                *(float2*)(out + (size_t)row * 1024 + col) = v;
            }
}

// ======================= attention pass 2: mask + softmax ===================
// One warp per row of attn (131072 rows x 1024). In place.
__global__ __launch_bounds__(256, 1)
void softmax_kernel(float* __restrict__ attn, const unsigned char* __restrict__ mask) {
    const int g = blockIdx.x * 8 + (threadIdx.x >> 5);   // row id
    const int lane = threadIdx.x & 31;
    const int q = g & 1023;
    const int b = (g >> 10) & 7;
    float4* row = (float4*)(attn + (size_t)g * 1024);
    const uchar4* mr = (const uchar4*)(mask + (size_t)(b * 1024 + q) * 1024);
    const float NEG_INF = __int_as_float(0xff800000);

    float4 v[8];
    float m = NEG_INF;
#pragma unroll
    for (int j = 0; j < 8; j++) {
        v[j] = row[lane + j * 32];
        uchar4 mm = mr[lane + j * 32];
        if (mm.x) v[j].x = NEG_INF;
        if (mm.y) v[j].y = NEG_INF;
        if (mm.z) v[j].z = NEG_INF;
        if (mm.w) v[j].w = NEG_INF;
        m = fmaxf(m, fmaxf(fmaxf(v[j].x, v[j].y), fmaxf(v[j].z, v[j].w)));
    }
#pragma unroll
    for (int o = 16; o > 0; o >>= 1) m = fmaxf(m, __shfl_xor_sync(0xffffffffu, m, o));
    float s = 0.0f;
#pragma unroll
    for (int j = 0; j < 8; j++) {
        v[j].x = __expf(v[j].x - m);
        v[j].y = __expf(v[j].y - m);
        v[j].z = __expf(v[j].z - m);
        v[j].w = __expf(v[j].w - m);
        s += v[j].x + v[j].y + v[j].z + v[j].w;
    }
#pragma unroll
    for (int o = 16; o > 0; o >>= 1) s += __shfl_xor_sync(0xffffffffu, s, o);
    const float inv = 1.0f / s;
#pragma unroll
    for (int j = 0; j < 8; j++) {
        v[j].x *= inv; v[j].y *= inv; v[j].z *= inv; v[j].w *= inv;
        row[lane + j * 32] = v[j];
    }
}

// ======================= attention pass 3: O = P V ==========================
// Per (h,b): M=1024, N=64, K=1024. P fp32 from attn (split inline),
// V pre-split bf16 [z*64+n][k]. CTA: 128 rows x 64 cols, K-chunk 32, 2 stages.
#define PVSTRIDE 80
#define PV_PT (128 * PVSTRIDE)    // 10240
#define PV_VT (64 * PVSTRIDE)     // 5120
#define PV_STAGE (2 * PV_PT + 2 * PV_VT)   // 30720
#define PV_SMEM (2 * PV_STAGE)             // 61440

__global__ __launch_bounds__(256, 1)
void pv_kernel(const float* __restrict__ attn,
               const __nv_bfloat16* __restrict__ VTh,
               const __nv_bfloat16* __restrict__ VTl,
               float* __restrict__ ctx) {
    extern __shared__ __align__(128) char sm[];
    const int t = threadIdx.x;
    const int wid = t >> 5, lane = t & 31;
    const int by = blockIdx.x, z = blockIdx.y;    // z = h*8+b
    const int h = z >> 3, b = z & 7;

    const float* Pb = attn + (size_t)z * 1024 * 1024 + (size_t)(by * 128) * 1024;
    const __nv_bfloat16* Vh = VTh + (size_t)z * 64 * 1024;
    const __nv_bfloat16* Vl = VTl + (size_t)z * 64 * 1024;

    float4 pr[4];
    uint4 vhr, vlr;
    const uint32_t smb = smem_u32(sm);
    const int wm = wid & 3;    // 4 x 32 rows
    const int wn = wid >> 2;   // 2 x 32 cols

    float acc[2][4][4];
#pragma unroll
    for (int mt = 0; mt < 2; mt++)
#pragma unroll
        for (int nt = 0; nt < 4; nt++)
#pragma unroll
            for (int j = 0; j < 4; j++) acc[mt][nt][j] = 0.0f;

    const uint32_t aoff = (uint32_t)((wm * 32 + (lane & 15)) * PVSTRIDE + (lane >> 4) * 16);
    const uint32_t boff = (uint32_t)((wn * 32 + (lane & 7) + ((lane >> 4) & 1) * 8) * PVSTRIDE
                                     + ((lane >> 3) & 1) * 16);
    const int vrow = t >> 2, vseg = t & 3;   // 64 rows x 4 segs of 16B

#define PV_LOAD(k0)                                                           \
    {                                                                         \
        _Pragma("unroll")                                                     \
        for (int i = 0; i < 4; i++) {                                         \
            int idx = t + 256 * i, row = idx >> 3, seg = idx & 7;             \
            pr[i] = *(const float4*)(Pb + (size_t)row * 1024 + (k0) + seg * 4); \
        }                                                                     \
        vhr = *(const uint4*)((const char*)(Vh + (size_t)vrow * 1024 + (k0)) + vseg * 16); \
        vlr = *(const uint4*)((const char*)(Vl + (size_t)vrow * 1024 + (k0)) + vseg * 16); \
    }

#define PV_STORE(buf)                                                         \
    {                                                                         \
        char* PH = sm + (buf) * PV_STAGE;                                     \
        char* PL = PH + PV_PT;                                                \
        char* VHs = PH + 2 * PV_PT;                                           \
        char* VLs = VHs + PV_VT;                                              \
        _Pragma("unroll")                                                     \
        for (int i = 0; i < 4; i++) {                                         \
            int idx = t + 256 * i, row = idx >> 3, seg = idx & 7;             \
            uint32_t h0, h1, l0, l1;                                          \
            split4(pr[i], h0, h1, l0, l1);                                    \
            *(uint2*)(PH + row * PVSTRIDE + seg * 8) = make_uint2(h0, h1);    \
            *(uint2*)(PL + row * PVSTRIDE + seg * 8) = make_uint2(l0, l1);    \
        }                                                                     \
        *(uint4*)(VHs + vrow * PVSTRIDE + vseg * 16) = vhr;                   \
        *(uint4*)(VLs + vrow * PVSTRIDE + vseg * 16) = vlr;                   \
    }

    PV_LOAD(0);
    PV_STORE(0);
    __syncthreads();

    for (int c = 0; c < 32; c++) {
        const int buf = c & 1;
        if (c + 1 < 32) PV_LOAD((c + 1) * 32);

        const uint32_t PHb = smb + buf * PV_STAGE;
        const uint32_t PLb = PHb + PV_PT;
        const uint32_t VHt = PHb + 2 * PV_PT;
        const uint32_t VLt = VHt + PV_VT;
#pragma unroll
        for (int ksd = 0; ksd < 2; ksd++) {
            const uint32_t kb = ksd * 32;
            uint32_t ah[2][4], al[2][4], bh[4][2], bl[4][2];
#pragma unroll
            for (int mt = 0; mt < 2; mt++) {
                ldsm4(ah[mt], PHb + aoff + mt * 16 * PVSTRIDE + kb);
                ldsm4(al[mt], PLb + aoff + mt * 16 * PVSTRIDE + kb);
            }
#pragma unroll
            for (int p = 0; p < 2; p++) {
                uint32_t r[4];
                ldsm4(r, VHt + boff + p * 16 * PVSTRIDE + kb);
                bh[2 * p][0] = r[0]; bh[2 * p][1] = r[1];
                bh[2 * p + 1][0] = r[2]; bh[2 * p + 1][1] = r[3];
                ldsm4(r, VLt + boff + p * 16 * PVSTRIDE + kb);
                bl[2 * p][0] = r[0]; bl[2 * p][1] = r[1];
                bl[2 * p + 1][0] = r[2]; bl[2 * p + 1][1] = r[3];
            }
#pragma unroll
            for (int mt = 0; mt < 2; mt++)
#pragma unroll
                for (int nt = 0; nt < 4; nt++) {
                    mma16816(acc[mt][nt], ah[mt], bh[nt]);
                    mma16816(acc[mt][nt], ah[mt], bl[nt]);
                    mma16816(acc[mt][nt], al[mt], bh[nt]);
                }
        }
        if (c + 1 < 32) {
            PV_STORE(buf ^ 1);
            __syncthreads();
        }
    }

    const int r0 = lane >> 2, c0 = (lane & 3) * 2;
#pragma unroll
    for (int mt = 0; mt < 2; mt++)
#pragma unroll
        for (int nt = 0; nt < 4; nt++)
#pragma unroll
            for (int half = 0; half < 2; half++) {
                int row = by * 128 + wm * 32 + mt * 16 + r0 + half * 8;
                int col = wn * 32 + nt * 8 + c0;
                float2 v = make_float2(acc[mt][nt][half * 2], acc[mt][nt][half * 2 + 1]);
                *(float2*)(ctx + (size_t)(b * 1024 + row) * 1024 + h * 64 + col) = v;
            }
#undef PV_LOAD
#undef PV_STORE
}

// ---------------------------------------------------------------------------
// In-place LayerNorm
// ---------------------------------------------------------------------------
__global__ void ln_kernel(float* __restrict__ y,
                          const float* __restrict__ gamma,
                          const float* __restrict__ beta) {
    __shared__ float red[18];
    const int row = blockIdx.x;
    const int t = threadIdx.x;
    float* p = y + (size_t)row * 1024;
    float v[4];
    float s = 0.0f, s2 = 0.0f;
#pragma unroll
    for (int j = 0; j < 4; j++) {
        v[j] = p[t + 256 * j];
        s += v[j];
        s2 += v[j] * v[j];
    }
#pragma unroll
    for (int o = 16; o > 0; o >>= 1) {
        s  += __shfl_xor_sync(0xffffffffu, s, o);
        s2 += __shfl_xor_sync(0xffffffffu, s2, o);
    }
    int warp = t >> 5, lane = t & 31;
    if (lane == 0) { red[warp] = s; red[8 + warp] = s2; }
    __syncthreads();
    if (t == 0) {
        float a = 0.0f, bsum = 0.0f;
#pragma unroll
        for (int w = 0; w < 8; w++) { a += red[w]; bsum += red[8 + w]; }
        red[16] = a; red[17] = bsum;
    }
    __syncthreads();
    float mean = red[16] * (1.0f / 1024.0f);
    float var  = red[17] * (1.0f / 1024.0f) - mean * mean;
    float inv  = rsqrtf(var + 1e-5f);
#pragma unroll
    for (int j = 0; j < 4; j++) {
        int c = t + 256 * j;
        p[c] = (v[j] - mean) * inv * gamma[c] + beta[c];
    }
}

// ---------------------------------------------------------------------------
// kernel_launch
// ---------------------------------------------------------------------------
extern "C" void kernel_launch(void* const* d_in, const int* in_sizes, int n_in,
                              void* d_out, int out_size) {
    const float* q      = (const float*)d_in[0];
    const float* k      = (const float*)d_in[1];
    const float* v      = (const float*)d_in[2];
    const unsigned char* mask = (const unsigned char*)d_in[3];
    const float* w_qs   = (const float*)d_in[4];
    const float* w_ks   = (const float*)d_in[5];
    const float* w_vs   = (const float*)d_in[6];
    const float* proj_w = (const float*)d_in[7];
    const float* proj_b = (const float*)d_in[8];
    const float* gamma  = (const float*)d_in[9];
    const float* beta   = (const float*)d_in[10];

    float* out = (float*)d_out;
    float* attn_out = out + (size_t)8192 * 1024;

    float* F = nullptr;  __nv_bfloat16* WB = nullptr;
    cudaGetSymbolAddress((void**)&F,  g_f32);
    cudaGetSymbolAddress((void**)&WB, g_wbf);

    float* QS  = F;
    float* KS  = F + (size_t)8  * M1;
    float* VS  = F + (size_t)16 * M1;
    float* CTX = F + (size_t)24 * M1;

    __nv_bfloat16* WQh = WB + 0 * M1; __nv_bfloat16* WQl = WB + 1 * M1;
    __nv_bfloat16* WKh = WB + 2 * M1; __nv_bfloat16* WKl = WB + 3 * M1;
    __nv_bfloat16* WVh = WB + 4 * M1; __nv_bfloat16* WVl = WB + 5 * M1;
    __nv_bfloat16* WPh = WB + 6 * M1; __nv_bfloat16* WPl = WB + 7 * M1;
    __nv_bfloat16* VTh = WB + (size_t)8  * M1;
    __nv_bfloat16* VTl = WB + (size_t)16 * M1;

    cudaFuncSetAttribute(gemm_mma_kernel<0>, cudaFuncAttributeMaxDynamicSharedMemorySize, GEMM_SMEM);
    cudaFuncSetAttribute(gemm_mma_kernel<1>, cudaFuncAttributeMaxDynamicSharedMemorySize, GEMM_SMEM);
    cudaFuncSetAttribute(qk_kernel, cudaFuncAttributeMaxDynamicSharedMemorySize, QK_SMEM);
    cudaFuncSetAttribute(pv_kernel, cudaFuncAttributeMaxDynamicSharedMemorySize, PV_SMEM);

    // weights -> bf16 hi/lo in [N,K] layout
    reshape_split_qkv<<<4096, 256>>>(w_qs, WQh, WQl);
    reshape_split_qkv<<<4096, 256>>>(w_ks, WKh, WKl);
    reshape_split_qkv<<<4096, 256>>>(w_vs, WVh, WVl);
    split_bf16_kernel<<<1024, 256>>>((const float4*)proj_w, (uint2*)WPh, (uint2*)WPl, 256 * 1024);

    const dim3 gg(8, 64);

    // QKV projections
    gemm_mma_kernel<0><<<gg, 256, GEMM_SMEM>>>(q, WQh, WQl, QS, nullptr, nullptr);
    gemm_mma_kernel<0><<<gg, 256, GEMM_SMEM>>>(k, WKh, WKl, KS, nullptr, nullptr);
    gemm_mma_kernel<0><<<gg, 256, GEMM_SMEM>>>(v, WVh, WVl, VS, nullptr, nullptr);

    // V transpose + split for PV pass
    vtrans_kernel<<<dim3(32, 2, 128), dim3(32, 8)>>>(VS, VTh, VTl);

    // attention: scores -> softmax (in place, in d_out) -> PV
    qk_kernel<<<dim3(8, 8, 128), 256, QK_SMEM>>>(QS, KS, attn_out);
    softmax_kernel<<<16384, 256>>>(attn_out, mask);
    pv_kernel<<<dim3(8, 128), 256, PV_SMEM>>>(attn_out, VTh, VTl, CTX);

    // output projection + bias + residual, then in-place LayerNorm
    gemm_mma_kernel<1><<<gg, 256, GEMM_SMEM>>>(CTX, WPh, WPl, out, proj_b, q);
    ln_kernel<<<8192, 256>>>(out, gamma, beta);
}